// round 17
// baseline (speedup 1.0000x reference)
#include <cuda_runtime.h>
#include <cstdint>

#define N_NODES 100000
#define N_EDGES 1600000
#define N_GRAPHS 256
#define IN_C 64
#define HID 128
#define BN_EPS 1e-5f
#define CK 32                    // weight k-chunk
#define SWS 136                  // weight chunk row stride (floats) -> B frag conflict-free
#define REGION_FL (128 * 132)    // z tile then hidden tile overlay
#define SW_FL (CK * SWS)         // one weight buffer
#define SCAN_BLKS ((N_NODES + 255) / 256)   // 391

// ---- tf32 helpers ----
__device__ __forceinline__ uint32_t f2tf(float f) {
    uint32_t u; asm("cvt.rna.tf32.f32 %0, %1;" : "=r"(u) : "f"(f)); return u;
}
__device__ __forceinline__ void mma_tf32(float (&d)[4], const uint32_t (&a)[4],
                                         uint32_t b0, uint32_t b1) {
    asm volatile(
        "mma.sync.aligned.m16n8k8.row.col.f32.tf32.tf32.f32 "
        "{%0,%1,%2,%3},{%4,%5,%6,%7},{%8,%9},{%0,%1,%2,%3};"
        : "+f"(d[0]), "+f"(d[1]), "+f"(d[2]), "+f"(d[3])
        : "r"(a[0]), "r"(a[1]), "r"(a[2]), "r"(a[3]), "r"(b0), "r"(b1));
}

// ---- inline BN finalize: (gamma,beta,stats) -> scale/shift for one column ----
__device__ __forceinline__ void bn_coeff(const float* __restrict__ gamma,
                                         const float* __restrict__ beta,
                                         const float* __restrict__ stats,
                                         int c, float& sc, float& sh) {
    float mean = stats[c] * (1.f / N_NODES);
    float var  = stats[HID + c] * (1.f / N_NODES) - mean * mean;
    float inv  = rsqrtf(var + BN_EPS);
    sc = gamma[c] * inv;
    sh = beta[c] - mean * sc;
}

// ---------------- scratch (device globals; no allocation) ----------------
__device__ float g_Z0[(size_t)N_NODES * HID];
__device__ float g_Z1[(size_t)N_NODES * HID];
__device__ float g_AGG[(size_t)N_NODES * HID];
__device__ float g_STATS[3 * 2 * HID];
__device__ float g_POOL[N_GRAPHS * HID];
__device__ int   g_DEG[N_NODES];
__device__ int   g_OFFS[N_NODES];
__device__ int   g_CURS[N_NODES];
__device__ int   g_BSUM[SCAN_BLKS];
__device__ int   g_CSR[N_EDGES];

// ---------------- init: zero stats + pool + deg in one launch ----------------
__global__ void init_kernel(float* stats, float* pool, int* deg) {
    int i = blockIdx.x * 256 + threadIdx.x;
    if (i < 3 * 2 * HID) stats[i] = 0.f;
    if (i < N_GRAPHS * HID) pool[i] = 0.f;
    if (i < N_NODES) deg[i] = 0;
}

// ================= CSR build =================
__global__ void hist_kernel(const int* __restrict__ ei, int* __restrict__ deg) {
    int e = blockIdx.x * blockDim.x + threadIdx.x;
    if (e < N_EDGES) atomicAdd(&deg[ei[N_EDGES + e]], 1);
}

__global__ void scan_block_kernel(const int* __restrict__ deg,
                                  int* __restrict__ offs, int* __restrict__ bsum) {
    __shared__ int s[256];
    int tid = threadIdx.x;
    int i = blockIdx.x * 256 + tid;
    int v = (i < N_NODES) ? deg[i] : 0;
    s[tid] = v;
    __syncthreads();
    #pragma unroll
    for (int d = 1; d < 256; d <<= 1) {
        int t = (tid >= d) ? s[tid - d] : 0;
        __syncthreads();
        s[tid] += t;
        __syncthreads();
    }
    if (i < N_NODES) offs[i] = s[tid] - v;
    if (tid == 255) bsum[blockIdx.x] = s[255];
}

__global__ void scan_bsum_kernel(int* __restrict__ bsum) {
    __shared__ int s[512];
    int tid = threadIdx.x;
    int v = (tid < SCAN_BLKS) ? bsum[tid] : 0;
    s[tid] = v;
    __syncthreads();
    #pragma unroll
    for (int d = 1; d < 512; d <<= 1) {
        int t = (tid >= d) ? s[tid - d] : 0;
        __syncthreads();
        s[tid] += t;
        __syncthreads();
    }
    if (tid < SCAN_BLKS) bsum[tid] = s[tid] - v;
}

__global__ void scan_add_kernel(int* __restrict__ offs, const int* __restrict__ bsum,
                                int* __restrict__ curs) {
    int i = blockIdx.x * 256 + threadIdx.x;
    if (i < N_NODES) {
        int o = offs[i] + bsum[blockIdx.x];
        offs[i] = o;
        curs[i] = o;
    }
}

__global__ void fill_kernel(const int* __restrict__ ei, int* __restrict__ curs,
                            int* __restrict__ csr) {
    int e = blockIdx.x * blockDim.x + threadIdx.x;
    if (e < N_EDGES) {
        int d = ei[N_EDGES + e];
        int slot = atomicAdd(&curs[d], 1);
        csr[slot] = ei[e];
    }
}

// ================= gather-aggregate (atomic-free, BN inline) =================
__global__ __launch_bounds__(256)
void gather64_kernel(const int* __restrict__ deg, const int* __restrict__ offs,
                     const int* __restrict__ csr, const float* __restrict__ z,
                     float* __restrict__ outz) {
    int node = (blockIdx.x * 256 + threadIdx.x) >> 5;
    if (node >= N_NODES) return;
    int lane = threadIdx.x & 31;
    int c = lane * 2;
    float2 acc = *(const float2*)(z + (size_t)node * IN_C + c);
    int beg = offs[node], n = deg[node];
    int e = 0;
    for (; e + 4 <= n; e += 4) {
        int s0 = csr[beg + e],     s1 = csr[beg + e + 1];
        int s2 = csr[beg + e + 2], s3 = csr[beg + e + 3];
        float2 v0 = *(const float2*)(z + (size_t)s0 * IN_C + c);
        float2 v1 = *(const float2*)(z + (size_t)s1 * IN_C + c);
        float2 v2 = *(const float2*)(z + (size_t)s2 * IN_C + c);
        float2 v3 = *(const float2*)(z + (size_t)s3 * IN_C + c);
        acc.x += (v0.x + v1.x) + (v2.x + v3.x);
        acc.y += (v0.y + v1.y) + (v2.y + v3.y);
    }
    for (; e < n; e++) {
        int s0 = csr[beg + e];
        float2 v0 = *(const float2*)(z + (size_t)s0 * IN_C + c);
        acc.x += v0.x; acc.y += v0.y;
    }
    *(float2*)(outz + (size_t)node * IN_C + c) = acc;
}

__device__ __forceinline__ float4 bnrelu4(float4 v, float4 sc, float4 sh) {
    float4 r;
    r.x = fmaxf(fmaf(v.x, sc.x, sh.x), 0.f);
    r.y = fmaxf(fmaf(v.y, sc.y, sh.y), 0.f);
    r.z = fmaxf(fmaf(v.z, sc.z, sh.z), 0.f);
    r.w = fmaxf(fmaf(v.w, sc.w, sh.w), 0.f);
    return r;
}

__global__ __launch_bounds__(256)
void gather128_kernel(const int* __restrict__ deg, const int* __restrict__ offs,
                      const int* __restrict__ csr, const float* __restrict__ z,
                      const float* __restrict__ gamma, const float* __restrict__ beta,
                      const float* __restrict__ stats,
                      float* __restrict__ outz) {
    int node = (blockIdx.x * 256 + threadIdx.x) >> 5;
    if (node >= N_NODES) return;
    int lane = threadIdx.x & 31;
    int c = lane * 4;
    float4 sc, sh;
    bn_coeff(gamma, beta, stats, c + 0, sc.x, sh.x);
    bn_coeff(gamma, beta, stats, c + 1, sc.y, sh.y);
    bn_coeff(gamma, beta, stats, c + 2, sc.z, sh.z);
    bn_coeff(gamma, beta, stats, c + 3, sc.w, sh.w);

    float4 vSelf = *(const float4*)(z + (size_t)node * HID + c);
    float4 a0 = bnrelu4(vSelf, sc, sh);
    float4 acc = a0;

    int beg = offs[node], n = deg[node];
    int e = 0;
    for (; e + 8 <= n; e += 8) {
        int s0 = csr[beg + e],     s1 = csr[beg + e + 1];
        int s2 = csr[beg + e + 2], s3 = csr[beg + e + 3];
        int s4 = csr[beg + e + 4], s5 = csr[beg + e + 5];
        int s6 = csr[beg + e + 6], s7 = csr[beg + e + 7];
        float4 v0 = *(const float4*)(z + (size_t)s0 * HID + c);
        float4 v1 = *(const float4*)(z + (size_t)s1 * HID + c);
        float4 v2 = *(const float4*)(z + (size_t)s2 * HID + c);
        float4 v3 = *(const float4*)(z + (size_t)s3 * HID + c);
        float4 v4 = *(const float4*)(z + (size_t)s4 * HID + c);
        float4 v5 = *(const float4*)(z + (size_t)s5 * HID + c);
        float4 v6 = *(const float4*)(z + (size_t)s6 * HID + c);
        float4 v7 = *(const float4*)(z + (size_t)s7 * HID + c);
        float4 b0 = bnrelu4(v0, sc, sh), b1 = bnrelu4(v1, sc, sh);
        float4 b2 = bnrelu4(v2, sc, sh), b3 = bnrelu4(v3, sc, sh);
        float4 b4 = bnrelu4(v4, sc, sh), b5 = bnrelu4(v5, sc, sh);
        float4 b6 = bnrelu4(v6, sc, sh), b7 = bnrelu4(v7, sc, sh);
        acc.x += ((b0.x + b1.x) + (b2.x + b3.x)) + ((b4.x + b5.x) + (b6.x + b7.x));
        acc.y += ((b0.y + b1.y) + (b2.y + b3.y)) + ((b4.y + b5.y) + (b6.y + b7.y));
        acc.z += ((b0.z + b1.z) + (b2.z + b3.z)) + ((b4.z + b5.z) + (b6.z + b7.z));
        acc.w += ((b0.w + b1.w) + (b2.w + b3.w)) + ((b4.w + b5.w) + (b6.w + b7.w));
    }
    for (; e + 2 <= n; e += 2) {
        int s0 = csr[beg + e], s1 = csr[beg + e + 1];
        float4 v0 = *(const float4*)(z + (size_t)s0 * HID + c);
        float4 v1 = *(const float4*)(z + (size_t)s1 * HID + c);
        float4 b0 = bnrelu4(v0, sc, sh), b1 = bnrelu4(v1, sc, sh);
        acc.x += b0.x + b1.x;
        acc.y += b0.y + b1.y;
        acc.z += b0.z + b1.z;
        acc.w += b0.w + b1.w;
    }
    if (e < n) {
        int s0 = csr[beg + e];
        float4 v0 = *(const float4*)(z + (size_t)s0 * HID + c);
        float4 b0 = bnrelu4(v0, sc, sh);
        acc.x += b0.x; acc.y += b0.y; acc.z += b0.z; acc.w += b0.w;
    }
    *(float4*)(outz + (size_t)node * HID + c) = acc;
}

// ---------------- fused MLP (tf32 mma.sync) — champion form ----------------
template <int CIN>
__global__ __launch_bounds__(256, 2)
void mlp_kernel(const float* __restrict__ zin,
                const float* __restrict__ w1, const float* __restrict__ b1,
                const float* __restrict__ w2, const float* __restrict__ b2,
                float* __restrict__ zout, float* __restrict__ stats) {
    extern __shared__ float sm[];
    float* region = sm;                     // REGION_FL (z tile, then hidden tile)
    float* swp    = sm + REGION_FL;         // SW_FL (weight chunk, tf32 bits)
    float* ssum   = swp + SW_FL;            // HID
    float* ssq    = ssum + HID;             // HID

    const int SZS = CIN + 4;                // z row stride (A frags conflict-free)
    const int tid  = threadIdx.x;
    const int row0 = blockIdx.x * 128;
    const int lane = tid & 31;
    const int wid  = tid >> 5;
    const int g    = lane >> 2;
    const int tig  = lane & 3;
    const int wm   = (wid & 3) * 32;
    const int n0   = (wid >> 2) * 64;

    if (tid < HID) { ssum[tid] = 0.f; ssq[tid] = 0.f; }

    // ---- stage z tile as tf32 bits ----
    {
        const int QPR = CIN / 4;
        #pragma unroll
        for (int t = 0; t < (128 * QPR) / 256; t++) {
            int i = t * 256 + tid;
            int r = i / QPR, q = i % QPR;
            int gr = row0 + r;
            float4 v = make_float4(0.f, 0.f, 0.f, 0.f);
            if (gr < N_NODES)
                v = *(const float4*)(zin + (size_t)gr * CIN + q * 4);
            uint4 u = make_uint4(f2tf(v.x), f2tf(v.y), f2tf(v.z), f2tf(v.w));
            *(uint4*)&region[r * SZS + q * 4] = u;
        }
    }

    float acc[2][8][4];

    // ======== GEMM1 ========
    {
        #pragma unroll
        for (int mt = 0; mt < 2; mt++)
            #pragma unroll
            for (int j = 0; j < 8; j++) {
                int c = n0 + j * 8 + 2 * tig;
                acc[mt][j][0] = b1[c]; acc[mt][j][1] = b1[c + 1];
                acc[mt][j][2] = b1[c]; acc[mt][j][3] = b1[c + 1];
            }

        const int NKC = CIN / CK;
        for (int kc = 0; kc < NKC; kc++) {
            __syncthreads();
            #pragma unroll
            for (int t = 0; t < 4; t++) {
                int i = t * 256 + tid;
                int k = i >> 5, seg = i & 31;
                float4 v = *(const float4*)(w1 + (size_t)(kc * CK + k) * HID + seg * 4);
                uint4 u = make_uint4(f2tf(v.x), f2tf(v.y), f2tf(v.z), f2tf(v.w));
                *(uint4*)&swp[k * SWS + seg * 4] = u;
            }
            __syncthreads();
            const uint32_t* zr = (const uint32_t*)region;
            const uint32_t* wr = (const uint32_t*)swp;
            #pragma unroll
            for (int ks = 0; ks < CK / 8; ks++) {
                int kb = ks * 8;
                int kg = kc * CK + kb + tig;
                uint32_t a[2][4];
                #pragma unroll
                for (int mt = 0; mt < 2; mt++) {
                    int rb = wm + mt * 16 + g;
                    a[mt][0] = zr[rb * SZS + kg];
                    a[mt][1] = zr[(rb + 8) * SZS + kg];
                    a[mt][2] = zr[rb * SZS + kg + 4];
                    a[mt][3] = zr[(rb + 8) * SZS + kg + 4];
                }
                #pragma unroll
                for (int j = 0; j < 8; j++) {
                    int cB = n0 + j * 8 + g;
                    uint32_t b0 = wr[(kb + tig) * SWS + cB];
                    uint32_t bq = wr[(kb + tig + 4) * SWS + cB];
                    mma_tf32(acc[0][j], a[0], b0, bq);
                    mma_tf32(acc[1][j], a[1], b0, bq);
                }
            }
        }
        __syncthreads();

        #pragma unroll
        for (int mt = 0; mt < 2; mt++)
            #pragma unroll
            for (int half = 0; half < 2; half++) {
                int row = wm + mt * 16 + half * 8 + g;
                #pragma unroll
                for (int j = 0; j < 8; j++) {
                    int c = n0 + j * 8 + 2 * tig;
                    uint2 u = make_uint2(
                        f2tf(fmaxf(acc[mt][j][half * 2 + 0], 0.f)),
                        f2tf(fmaxf(acc[mt][j][half * 2 + 1], 0.f)));
                    *(uint2*)&region[row * 132 + c] = u;
                }
            }
    }

    // ======== GEMM2 ========
    {
        #pragma unroll
        for (int mt = 0; mt < 2; mt++)
            #pragma unroll
            for (int j = 0; j < 8; j++) {
                int c = n0 + j * 8 + 2 * tig;
                acc[mt][j][0] = b2[c]; acc[mt][j][1] = b2[c + 1];
                acc[mt][j][2] = b2[c]; acc[mt][j][3] = b2[c + 1];
            }

        for (int kc = 0; kc < HID / CK; kc++) {
            __syncthreads();
            #pragma unroll
            for (int t = 0; t < 4; t++) {
                int i = t * 256 + tid;
                int k = i >> 5, seg = i & 31;
                float4 v = *(const float4*)(w2 + (size_t)(kc * CK + k) * HID + seg * 4);
                uint4 u = make_uint4(f2tf(v.x), f2tf(v.y), f2tf(v.z), f2tf(v.w));
                *(uint4*)&swp[k * SWS + seg * 4] = u;
            }
            __syncthreads();
            const uint32_t* hr = (const uint32_t*)region;
            const uint32_t* wr = (const uint32_t*)swp;
            #pragma unroll
            for (int ks = 0; ks < CK / 8; ks++) {
                int kb = ks * 8;
                int kg = kc * CK + kb + tig;
                uint32_t a[2][4];
                #pragma unroll
                for (int mt = 0; mt < 2; mt++) {
                    int rb = wm + mt * 16 + g;
                    a[mt][0] = hr[rb * 132 + kg];
                    a[mt][1] = hr[(rb + 8) * 132 + kg];
                    a[mt][2] = hr[rb * 132 + kg + 4];
                    a[mt][3] = hr[(rb + 8) * 132 + kg + 4];
                }
                #pragma unroll
                for (int j = 0; j < 8; j++) {
                    int cB = n0 + j * 8 + g;
                    uint32_t b0 = wr[(kb + tig) * SWS + cB];
                    uint32_t bq = wr[(kb + tig + 4) * SWS + cB];
                    mma_tf32(acc[0][j], a[0], b0, bq);
                    mma_tf32(acc[1][j], a[1], b0, bq);
                }
            }
        }
    }

    // ======== epilogue ========
    float s[16], q[16];
    #pragma unroll
    for (int j = 0; j < 16; j++) { s[j] = 0.f; q[j] = 0.f; }

    #pragma unroll
    for (int mt = 0; mt < 2; mt++)
        #pragma unroll
        for (int half = 0; half < 2; half++) {
            int gr = row0 + wm + mt * 16 + half * 8 + g;
            if (gr < N_NODES) {
                #pragma unroll
                for (int j = 0; j < 8; j++) {
                    float v0 = acc[mt][j][half * 2 + 0];
                    float v1 = acc[mt][j][half * 2 + 1];
                    int c = n0 + j * 8 + 2 * tig;
                    *(float2*)&zout[(size_t)gr * HID + c] = make_float2(v0, v1);
                    s[2 * j] += v0;     q[2 * j] += v0 * v0;
                    s[2 * j + 1] += v1; q[2 * j + 1] += v1 * v1;
                }
            }
        }
    #pragma unroll
    for (int j = 0; j < 8; j++) {
        int c = n0 + j * 8 + 2 * tig;
        atomicAdd(&ssum[c], s[2 * j]);
        atomicAdd(&ssq[c], q[2 * j]);
        atomicAdd(&ssum[c + 1], s[2 * j + 1]);
        atomicAdd(&ssq[c + 1], q[2 * j + 1]);
    }
    __syncthreads();
    if (tid < HID) {
        atomicAdd(&stats[tid], ssum[tid]);
        atomicAdd(&stats[HID + tid], ssq[tid]);
    }
}

// ---------------- mean pool with inline BN+relu (batch sorted) ----------------
__global__ void pool_kernel(const float* __restrict__ z, const int* __restrict__ batch,
                            const float* __restrict__ gamma, const float* __restrict__ beta,
                            const float* __restrict__ stats,
                            float* __restrict__ pool) {
    __shared__ int sb[256];
    int r0  = blockIdx.x * 256;
    int tid = threadIdx.x;  // 128 threads, one column each
    for (int i = tid; i < 256; i += 128) {
        int gr = r0 + i;
        sb[i] = (gr < N_NODES) ? batch[gr] : -1;
    }
    __syncthreads();
    int c = tid;
    float sc, sh;
    bn_coeff(gamma, beta, stats, c, sc, sh);
    float sum = 0.f;
    int cur = sb[0];
    for (int i = 0; i < 256; i++) {
        int gr = r0 + i;
        if (gr >= N_NODES) break;
        int b = sb[i];
        if (b != cur) {
            atomicAdd(&pool[cur * HID + c], sum);
            sum = 0.f; cur = b;
        }
        sum += fmaxf(fmaf(z[(long long)gr * HID + c], sc, sh), 0.f);
    }
    if (cur >= 0) atomicAdd(&pool[cur * HID + c], sum);
}

// ---------------- final projection with inline per-graph count ----------------
__global__ void proj_kernel(const float* __restrict__ w, const float* __restrict__ b,
                            const float* __restrict__ pool, const int* __restrict__ batch,
                            float* __restrict__ out) {
    __shared__ float hg[HID];
    int g = blockIdx.x, t = threadIdx.x;
    // per-graph count via binary search (redundant across threads; L2-resident)
    int lo = 0, hi = N_NODES;
    while (lo < hi) { int m = (lo + hi) >> 1; if (batch[m] < g) lo = m + 1; else hi = m; }
    int a = lo;
    lo = 0; hi = N_NODES;
    while (lo < hi) { int m = (lo + hi) >> 1; if (batch[m] < g + 1) lo = m + 1; else hi = m; }
    float cinv = 1.f / fmaxf((float)(lo - a), 1.f);

    hg[t] = pool[g * HID + t] * cinv;
    __syncthreads();
    float acc = b[t];
    #pragma unroll 8
    for (int k = 0; k < HID; k++) acc = fmaf(hg[k], w[k * HID + t], acc);
    out[g * HID + t] = acc;
}

// ---------------- host orchestration ----------------
static void* sym(const void* s) {
    void* p = nullptr;
    cudaGetSymbolAddress(&p, s);
    return p;
}

extern "C" void kernel_launch(void* const* d_in, const int* in_sizes, int n_in,
                              void* d_out, int out_size) {
    const float* x     = (const float*)d_in[0];
    const int*   ei    = (const int*)d_in[1];
    const int*   batch = (const int*)d_in[2];
    const float* L[3][6];
    for (int l = 0; l < 3; l++)
        for (int k = 0; k < 6; k++) L[l][k] = (const float*)d_in[3 + 6 * l + k];
    const float* proj_w = (const float*)d_in[21];
    const float* proj_b = (const float*)d_in[22];
    float* out = (float*)d_out;

    float* Z0    = (float*)sym(g_Z0);
    float* Z1    = (float*)sym(g_Z1);
    float* AGG   = (float*)sym(g_AGG);
    float* STATS = (float*)sym(g_STATS);
    float* POOL  = (float*)sym(g_POOL);
    int*   DEG   = (int*)sym(g_DEG);
    int*   OFFS  = (int*)sym(g_OFFS);
    int*   CURS  = (int*)sym(g_CURS);
    int*   BSUM  = (int*)sym(g_BSUM);
    int*   CSR   = (int*)sym(g_CSR);

    const int smemMlp = (REGION_FL + SW_FL + 2 * HID) * 4;   // ~86 KB -> 2 CTAs/SM
    cudaFuncSetAttribute(mlp_kernel<IN_C>, cudaFuncAttributeMaxDynamicSharedMemorySize, smemMlp);
    cudaFuncSetAttribute(mlp_kernel<HID>,  cudaFuncAttributeMaxDynamicSharedMemorySize, smemMlp);

    const int mlpBlocks  = (N_NODES + 127) / 128;
    const int edgeBlocks = (N_EDGES + 255) / 256;
    const int gathBlocks = (N_NODES * 32 + 255) / 256;   // warp per node

    // ---- init (stats + pool + deg) ----
    init_kernel<<<SCAN_BLKS, 256>>>(STATS, POOL, DEG);

    // ---- CSR build (reused by all 3 layers) ----
    hist_kernel<<<edgeBlocks, 256>>>(ei, DEG);
    scan_block_kernel<<<SCAN_BLKS, 256>>>(DEG, OFFS, BSUM);
    scan_bsum_kernel<<<1, 512>>>(BSUM);
    scan_add_kernel<<<SCAN_BLKS, 256>>>(OFFS, BSUM, CURS);
    fill_kernel<<<edgeBlocks, 256>>>(ei, CURS, CSR);

    // ---- layer 0 (CIN=64): z_in = x + sum_N x ----
    gather64_kernel<<<gathBlocks, 256>>>(DEG, OFFS, CSR, x, AGG);
    mlp_kernel<IN_C><<<mlpBlocks, 256, smemMlp>>>(
        AGG, L[0][0], L[0][1], L[0][2], L[0][3], Z0, STATS);

    // ---- layers 1,2 (CIN=128), BN of previous layer inlined in gather ----
    const float* zprev = Z0;
    float* zcur = Z1;
    for (int l = 1; l < 3; l++) {
        gather128_kernel<<<gathBlocks, 256>>>(
            DEG, OFFS, CSR, zprev, L[l - 1][4], L[l - 1][5],
            STATS + (l - 1) * 2 * HID, AGG);
        mlp_kernel<HID><<<mlpBlocks, 256, smemMlp>>>(
            AGG, L[l][0], L[l][1], L[l][2], L[l][3], zcur, STATS + l * 2 * HID);
        const float* t = zprev; zprev = zcur; zcur = (float*)t;
    }

    // ---- pool (BN of layer 2 inlined) + projection (count inlined) ----
    pool_kernel<<<(N_NODES + 255) / 256, 128>>>(
        zprev, batch, L[2][4], L[2][5], STATS + 2 * 2 * HID, POOL);
    proj_kernel<<<N_GRAPHS, HID>>>(proj_w, proj_b, POOL, batch, out);
}